// round 1
// baseline (speedup 1.0000x reference)
#include <cuda_runtime.h>
#include <cuda_bf16.h>
#include <math.h>

#define BATCH 1024
#define SEQ   512
#define HID   64
#define GATES 256   // 4*HID
#define BC    8     // batch rows per CTA

// Scratch: layer-0 hidden sequence (input to layer 1). 128 MB static device array.
__device__ float g_h1[(size_t)BATCH * SEQ * HID];

__device__ __forceinline__ float sigf(float x) { return 1.0f / (1.0f + expf(-x)); }

// One LSTM layer, fully fused over time. Each CTA owns BC batch rows; the
// recurrence only couples within a batch row, so CTAs never synchronize.
// Thread g (0..255) owns gate row g of w_ih and w_hh in registers.
// LAYER==0: xin = d_x, writes g_h1.  LAYER==1: reads g_h1, fused FC -> out.
template<int LAYER>
__global__ void __launch_bounds__(256, 1) lstm_layer_kernel(
    const float* __restrict__ xin,
    const float* __restrict__ w_ih,   // [256][64]
    const float* __restrict__ w_hh,   // [256][64]
    const float* __restrict__ b_ih,   // [256]
    const float* __restrict__ b_hh,   // [256]
    const float* __restrict__ fc_w,   // [64]  (LAYER==1 only)
    const float* __restrict__ fc_b,   // [1]   (LAYER==1 only)
    float* __restrict__ out)          // [BATCH] (LAYER==1 only)
{
    __shared__ __align__(16) float sx[2][BC][HID];   // double-buffered x_t slice
    __shared__ __align__(16) float sh[BC][HID];      // h_{t-1}
    __shared__ __align__(16) float spre[BC][GATES];  // gate pre-activations

    const int tid  = threadIdx.x;
    const int g    = tid;            // gate row this thread owns
    const int b0   = blockIdx.x * BC;
    const int wrp  = tid >> 5;
    const int lane = tid & 31;

    const float* in = (LAYER == 0) ? xin : g_h1;

    // Weights resident in registers: 128 floats/thread.
    float wih[HID], whh[HID];
#pragma unroll
    for (int k = 0; k < HID; k++) {
        wih[k] = w_ih[g * HID + k];
        whh[k] = w_hh[g * HID + k];
    }
    const float bias = b_ih[g] + b_hh[g];

    // h0 = 0, c0 = 0.  Each thread owns 2 cells: cidx = tid and tid+256,
    // with b = cidx>>6, j = cidx&63 (mapping fixed across all steps).
    ((float*)sh)[tid]       = 0.0f;
    ((float*)sh)[tid + 256] = 0.0f;
    float c0 = 0.0f, c1 = 0.0f;

    // Preload x_t for t=0: warp w loads row w (64 floats), 2 per lane.
    {
        const float* src = in + ((size_t)(b0 + wrp) * SEQ) * HID;
        *(float2*)&sx[0][wrp][lane * 2] = *(const float2*)&src[lane * 2];
    }
    __syncthreads();

    for (int t = 0; t < SEQ; t++) {
        const int cur = t & 1;

        // Prefetch x_{t+1} into the other buffer; latency hidden by FMA phase.
        if (t + 1 < SEQ) {
            const float* src = in + ((size_t)(b0 + wrp) * SEQ + (t + 1)) * HID;
            *(float2*)&sx[cur ^ 1][wrp][lane * 2] = *(const float2*)&src[lane * 2];
        }

        // Phase 1: gate pre-activations.  acc[b] = bias + x_t.wih + h.whh
        float acc[BC];
#pragma unroll
        for (int b = 0; b < BC; b++) acc[b] = bias;

#pragma unroll
        for (int k = 0; k < HID; k += 4) {
#pragma unroll
            for (int b = 0; b < BC; b++) {
                const float4 xv = *(const float4*)&sx[cur][b][k];
                const float4 hv = *(const float4*)&sh[b][k];
                acc[b] = fmaf(xv.x, wih[k + 0], acc[b]);
                acc[b] = fmaf(xv.y, wih[k + 1], acc[b]);
                acc[b] = fmaf(xv.z, wih[k + 2], acc[b]);
                acc[b] = fmaf(xv.w, wih[k + 3], acc[b]);
                acc[b] = fmaf(hv.x, whh[k + 0], acc[b]);
                acc[b] = fmaf(hv.y, whh[k + 1], acc[b]);
                acc[b] = fmaf(hv.z, whh[k + 2], acc[b]);
                acc[b] = fmaf(hv.w, whh[k + 3], acc[b]);
            }
        }
#pragma unroll
        for (int b = 0; b < BC; b++) spre[b][g] = acc[b];
        __syncthreads();

        // Phase 2: cell/hidden update; 2 cells per thread.
#pragma unroll
        for (int cc = 0; cc < 2; cc++) {
            const int cidx = tid + cc * 256;
            const int b = cidx >> 6, j = cidx & 63;
            const float iv = sigf(spre[b][j]);
            const float fv = sigf(spre[b][64 + j]);
            const float gv = tanhf(spre[b][128 + j]);
            const float ov = sigf(spre[b][192 + j]);
            float& c = cc ? c1 : c0;
            c = fv * c + iv * gv;
            const float h = ov * tanhf(c);
            sh[b][j] = h;
            if (LAYER == 0)
                g_h1[((size_t)(b0 + b) * SEQ + t) * HID + j] = h;
        }
        __syncthreads();
    }

    // Fused FC head on the final hidden state (layer 1 only).
    if (LAYER == 1) {
        float v = fc_w[lane] * sh[wrp][lane] + fc_w[lane + 32] * sh[wrp][lane + 32];
#pragma unroll
        for (int off = 16; off; off >>= 1)
            v += __shfl_down_sync(0xffffffffu, v, off);
        if (lane == 0) out[b0 + wrp] = v + fc_b[0];
    }
}

extern "C" void kernel_launch(void* const* d_in, const int* in_sizes, int n_in,
                              void* d_out, int out_size)
{
    const float* x     = (const float*)d_in[0];
    const float* w_ih0 = (const float*)d_in[1];
    const float* w_hh0 = (const float*)d_in[2];
    const float* b_ih0 = (const float*)d_in[3];
    const float* b_hh0 = (const float*)d_in[4];
    const float* w_ih1 = (const float*)d_in[5];
    const float* w_hh1 = (const float*)d_in[6];
    const float* b_ih1 = (const float*)d_in[7];
    const float* b_hh1 = (const float*)d_in[8];
    const float* fc_w  = (const float*)d_in[9];
    const float* fc_b  = (const float*)d_in[10];
    float* out = (float*)d_out;

    dim3 grid(BATCH / BC);
    lstm_layer_kernel<0><<<grid, 256>>>(x, w_ih0, w_hh0, b_ih0, b_hh0,
                                        nullptr, nullptr, nullptr);
    lstm_layer_kernel<1><<<grid, 256>>>(nullptr, w_ih1, w_hh1, b_ih1, b_hh1,
                                        fc_w, fc_b, out);
}

// round 2
// speedup vs baseline: 1.1597x; 1.1597x over previous
#include <cuda_runtime.h>
#include <cuda_bf16.h>
#include <math.h>

#define BATCH 1024
#define SEQ   512
#define HID   64
#define GATES 256   // 4*HID
#define BC    8     // batch rows per CTA

// Scratch: layer-0 hidden sequence (input to layer 1). 128 MB static device array.
__device__ float g_h1[(size_t)BATCH * SEQ * HID];

typedef unsigned long long u64;

// Packed fp32x2 FMA: d = a*b + d  (Blackwell FFMA2, only reachable via PTX).
__device__ __forceinline__ void ffma2(u64& d, u64 a, u64 b) {
    asm("fma.rn.f32x2 %0, %1, %2, %0;" : "+l"(d) : "l"(a), "l"(b));
}
__device__ __forceinline__ u64 pack2(float lo, float hi) {
    u64 r; asm("mov.b64 %0, {%1, %2};" : "=l"(r) : "f"(lo), "f"(hi)); return r;
}
__device__ __forceinline__ float2 unpack2(u64 v) {
    float lo, hi; asm("mov.b64 {%0, %1}, %2;" : "=f"(lo), "=f"(hi) : "l"(v));
    return make_float2(lo, hi);
}

// Fast, still-accurate activations (MUFU.EX2 / MUFU.RCP based, err ~1e-6).
__device__ __forceinline__ float sig_fast(float x) {
    return __fdividef(1.0f, 1.0f + __expf(-x));
}
__device__ __forceinline__ float tanh_fast(float x) {
    float e = __expf(-2.0f * fabsf(x));
    float t = __fdividef(1.0f - e, 1.0f + e);
    return copysignf(t, x);
}

// One LSTM layer, fused over all SEQ steps. Each CTA owns BC batch rows (no
// inter-CTA coupling). Thread g owns gate row g of w_ih/w_hh packed as f32x2
// pairs in registers. LAYER==0: reads x, writes g_h1. LAYER==1: reads g_h1,
// fused FC head -> out.
template<int LAYER>
__global__ void __launch_bounds__(256, 1) lstm_layer_kernel(
    const float* __restrict__ xin,
    const float* __restrict__ w_ih,   // [256][64]
    const float* __restrict__ w_hh,   // [256][64]
    const float* __restrict__ b_ih,   // [256]
    const float* __restrict__ b_hh,   // [256]
    const float* __restrict__ fc_w,   // [64]  (LAYER==1 only)
    const float* __restrict__ fc_b,   // [1]   (LAYER==1 only)
    float* __restrict__ out)          // [BATCH] (LAYER==1 only)
{
    __shared__ __align__(16) float sx[2][BC][HID];   // double-buffered x_t
    __shared__ __align__(16) float sh[BC][HID];      // h_{t-1}
    __shared__ __align__(16) float spre[BC][GATES];  // gate pre-activations

    const int tid  = threadIdx.x;
    const int g    = tid;
    const int b0   = blockIdx.x * BC;
    const int wrp  = tid >> 5;
    const int lane = tid & 31;

    const float* in = (LAYER == 0) ? xin : g_h1;

    // Weights in registers as 32+32 packed f32x2 pairs (128 regs).
    u64 wih2[HID / 2], whh2[HID / 2];
#pragma unroll
    for (int k = 0; k < HID / 2; k++) {
        const float2 a = *(const float2*)&w_ih[g * HID + 2 * k];
        const float2 b = *(const float2*)&w_hh[g * HID + 2 * k];
        wih2[k] = pack2(a.x, a.y);
        whh2[k] = pack2(b.x, b.y);
    }
    const float bias = b_ih[g] + b_hh[g];

    ((float*)sh)[tid]       = 0.0f;
    ((float*)sh)[tid + 256] = 0.0f;
    float c0 = 0.0f, c1 = 0.0f;

    // Preload x_0: warp w loads batch row w (64 floats, 2/lane).
    {
        const float* src = in + ((size_t)(b0 + wrp) * SEQ) * HID;
        *(float2*)&sx[0][wrp][lane * 2] = *(const float2*)&src[lane * 2];
    }
    __syncthreads();

    for (int t = 0; t < SEQ; t++) {
        const int cur = t & 1;

        // Prefetch x_{t+1}; latency hidden under the FMA phase.
        if (t + 1 < SEQ) {
            const float* src = in + ((size_t)(b0 + wrp) * SEQ + (t + 1)) * HID;
            *(float2*)&sx[cur ^ 1][wrp][lane * 2] = *(const float2*)&src[lane * 2];
        }

        // Phase 1: gate pre-activations via packed f32x2 FMAs.
        u64 acc[BC];
#pragma unroll
        for (int b = 0; b < BC; b++) acc[b] = 0ull;

#pragma unroll
        for (int k = 0; k < HID; k += 4) {
            const int p = k >> 1;
#pragma unroll
            for (int b = 0; b < BC; b++) {
                const ulonglong2 xv = *(const ulonglong2*)&sx[cur][b][k];
                const ulonglong2 hv = *(const ulonglong2*)&sh[b][k];
                ffma2(acc[b], xv.x, wih2[p]);
                ffma2(acc[b], xv.y, wih2[p + 1]);
                ffma2(acc[b], hv.x, whh2[p]);
                ffma2(acc[b], hv.y, whh2[p + 1]);
            }
        }
#pragma unroll
        for (int b = 0; b < BC; b++) {
            const float2 s = unpack2(acc[b]);
            spre[b][g] = s.x + s.y + bias;
        }
        __syncthreads();

        // Phase 2: cell/hidden update; 2 cells per thread.
#pragma unroll
        for (int cc = 0; cc < 2; cc++) {
            const int cidx = tid + cc * 256;
            const int b = cidx >> 6, j = cidx & 63;
            const float iv = sig_fast(spre[b][j]);
            const float fv = sig_fast(spre[b][64 + j]);
            const float gv = tanh_fast(spre[b][128 + j]);
            const float ov = sig_fast(spre[b][192 + j]);
            float& c = cc ? c1 : c0;
            c = fv * c + iv * gv;
            const float h = ov * tanh_fast(c);
            sh[b][j] = h;
            if (LAYER == 0)
                g_h1[((size_t)(b0 + b) * SEQ + t) * HID + j] = h;
        }
        __syncthreads();
    }

    // Fused FC head on the final hidden state (layer 1 only).
    if (LAYER == 1) {
        float v = fc_w[lane] * sh[wrp][lane] + fc_w[lane + 32] * sh[wrp][lane + 32];
#pragma unroll
        for (int off = 16; off; off >>= 1)
            v += __shfl_down_sync(0xffffffffu, v, off);
        if (lane == 0) out[b0 + wrp] = v + fc_b[0];
    }
}

extern "C" void kernel_launch(void* const* d_in, const int* in_sizes, int n_in,
                              void* d_out, int out_size)
{
    const float* x     = (const float*)d_in[0];
    const float* w_ih0 = (const float*)d_in[1];
    const float* w_hh0 = (const float*)d_in[2];
    const float* b_ih0 = (const float*)d_in[3];
    const float* b_hh0 = (const float*)d_in[4];
    const float* w_ih1 = (const float*)d_in[5];
    const float* w_hh1 = (const float*)d_in[6];
    const float* b_ih1 = (const float*)d_in[7];
    const float* b_hh1 = (const float*)d_in[8];
    const float* fc_w  = (const float*)d_in[9];
    const float* fc_b  = (const float*)d_in[10];
    float* out = (float*)d_out;

    dim3 grid(BATCH / BC);
    lstm_layer_kernel<0><<<grid, 256>>>(x, w_ih0, w_hh0, b_ih0, b_hh0,
                                        nullptr, nullptr, nullptr);
    lstm_layer_kernel<1><<<grid, 256>>>(nullptr, w_ih1, w_hh1, b_ih1, b_hh1,
                                        fc_w, fc_b, out);
}

// round 3
// speedup vs baseline: 1.1811x; 1.0185x over previous
#include <cuda_runtime.h>
#include <cuda_bf16.h>
#include <math.h>

#define BATCH 1024
#define SEQ   512
#define HID   64
#define GATES 256   // 4*HID
#define BC    8     // batch rows per CTA
#define NT    512   // threads per CTA (split-K by 2)

// Scratch: layer-0 hidden sequence (input to layer 1). 128 MB static device array.
__device__ float g_h1[(size_t)BATCH * SEQ * HID];

typedef unsigned long long u64;

// Packed fp32x2 FMA: d = a*b + d  (Blackwell FFMA2, only reachable via PTX).
__device__ __forceinline__ void ffma2(u64& d, u64 a, u64 b) {
    asm("fma.rn.f32x2 %0, %1, %2, %0;" : "+l"(d) : "l"(a), "l"(b));
}
__device__ __forceinline__ u64 pack2(float lo, float hi) {
    u64 r; asm("mov.b64 %0, {%1, %2};" : "=l"(r) : "f"(lo), "f"(hi)); return r;
}
__device__ __forceinline__ float2 unpack2(u64 v) {
    float lo, hi; asm("mov.b64 {%0, %1}, %2;" : "=f"(lo), "=f"(hi) : "l"(v));
    return make_float2(lo, hi);
}

// Fast activations (MUFU.EX2 / MUFU.RCP based, err ~1e-6 — budget is 1e-3).
__device__ __forceinline__ float sig_fast(float x) {
    return __fdividef(1.0f, 1.0f + __expf(-x));
}
__device__ __forceinline__ float tanh_fast(float x) {
    float e = __expf(-2.0f * fabsf(x));
    float t = __fdividef(1.0f - e, 1.0f + e);
    return copysignf(t, x);
}

// One LSTM layer, fused over all SEQ steps. Each CTA owns BC batch rows (no
// inter-CTA coupling). Split-K: thread (g, half) owns k-range [half*32, half*32+32)
// of gate row g; the two halves accumulate into separate spre planes that
// phase 2 sums (no extra barrier). 512 threads -> 16 warps/SM.
template<int LAYER>
__global__ void __launch_bounds__(NT, 1) lstm_layer_kernel(
    const float* __restrict__ xin,
    const float* __restrict__ w_ih,   // [256][64]
    const float* __restrict__ w_hh,   // [256][64]
    const float* __restrict__ b_ih,   // [256]
    const float* __restrict__ b_hh,   // [256]
    const float* __restrict__ fc_w,   // [64]  (LAYER==1 only)
    const float* __restrict__ fc_b,   // [1]   (LAYER==1 only)
    float* __restrict__ out)          // [BATCH] (LAYER==1 only)
{
    __shared__ __align__(16) float sx[2][BC][HID];       // double-buffered x_t
    __shared__ __align__(16) float sh[BC][HID];          // h_{t-1}
    __shared__ __align__(16) float spre[2][BC][GATES];   // split-K partials

    const int tid  = threadIdx.x;
    const int g    = tid & 255;        // gate row
    const int half = tid >> 8;         // k-half: 0 or 1
    const int kb   = half * 32;        // k base
    const int b0   = blockIdx.x * BC;
    const int bb   = tid >> 6;         // cell batch index (phase 2 / loads)
    const int jj   = tid & 63;         // cell hidden index

    const float* in = (LAYER == 0) ? xin : g_h1;

    // Weights in registers: 16+16 packed f32x2 pairs (64 regs).
    u64 wih2[16], whh2[16];
#pragma unroll
    for (int k = 0; k < 16; k++) {
        const float2 a = *(const float2*)&w_ih[g * HID + kb + 2 * k];
        const float2 b = *(const float2*)&w_hh[g * HID + kb + 2 * k];
        wih2[k] = pack2(a.x, a.y);
        whh2[k] = pack2(b.x, b.y);
    }
    const float bias = (half == 0) ? (b_ih[g] + b_hh[g]) : 0.0f;

    // h0 = c0 = 0. Each thread owns cell (bb, jj).
    if (half == 0) ((float*)sh)[tid] = 0.0f;
    float c = 0.0f;

    // Preload x_0: one float per thread, coalesced.
    sx[0][bb][jj] = in[((size_t)(b0 + bb) * SEQ) * HID + jj];
    __syncthreads();

    for (int t = 0; t < SEQ; t++) {
        const int cur = t & 1;

        // Prefetch x_{t+1}; latency hidden under the FMA phase.
        if (t + 1 < SEQ)
            sx[cur ^ 1][bb][jj] = in[((size_t)(b0 + bb) * SEQ + (t + 1)) * HID + jj];

        // Phase 1: partial gate pre-activations over this thread's k-half.
        u64 acc[BC];
#pragma unroll
        for (int b = 0; b < BC; b++) acc[b] = 0ull;

#pragma unroll
        for (int k = 0; k < 32; k += 4) {
            const int p = k >> 1;
#pragma unroll
            for (int b = 0; b < BC; b++) {
                const ulonglong2 xv = *(const ulonglong2*)&sx[cur][b][kb + k];
                const ulonglong2 hv = *(const ulonglong2*)&sh[b][kb + k];
                ffma2(acc[b], xv.x, wih2[p]);
                ffma2(acc[b], xv.y, wih2[p + 1]);
                ffma2(acc[b], hv.x, whh2[p]);
                ffma2(acc[b], hv.y, whh2[p + 1]);
            }
        }
#pragma unroll
        for (int b = 0; b < BC; b++) {
            const float2 s = unpack2(acc[b]);
            spre[half][b][g] = s.x + s.y + bias;
        }
        __syncthreads();

        // Phase 2: one cell per thread; sum the two split-K planes.
        {
            const float pi = spre[0][bb][jj]       + spre[1][bb][jj];
            const float pf = spre[0][bb][64 + jj]  + spre[1][bb][64 + jj];
            const float pg = spre[0][bb][128 + jj] + spre[1][bb][128 + jj];
            const float po = spre[0][bb][192 + jj] + spre[1][bb][192 + jj];
            const float iv = sig_fast(pi);
            const float fv = sig_fast(pf);
            const float gv = tanh_fast(pg);
            const float ov = sig_fast(po);
            c = fv * c + iv * gv;
            const float h = ov * tanh_fast(c);
            sh[bb][jj] = h;
            if (LAYER == 0)
                g_h1[((size_t)(b0 + bb) * SEQ + t) * HID + jj] = h;
        }
        __syncthreads();
    }

    // Fused FC head on the final hidden state (layer 1 only).
    if (LAYER == 1 && tid < 256) {
        const int wrp  = tid >> 5;
        const int lane = tid & 31;
        float v = fc_w[lane] * sh[wrp][lane] + fc_w[lane + 32] * sh[wrp][lane + 32];
#pragma unroll
        for (int off = 16; off; off >>= 1)
            v += __shfl_down_sync(0xffffffffu, v, off);
        if (lane == 0) out[b0 + wrp] = v + fc_b[0];
    }
}

extern "C" void kernel_launch(void* const* d_in, const int* in_sizes, int n_in,
                              void* d_out, int out_size)
{
    const float* x     = (const float*)d_in[0];
    const float* w_ih0 = (const float*)d_in[1];
    const float* w_hh0 = (const float*)d_in[2];
    const float* b_ih0 = (const float*)d_in[3];
    const float* b_hh0 = (const float*)d_in[4];
    const float* w_ih1 = (const float*)d_in[5];
    const float* w_hh1 = (const float*)d_in[6];
    const float* b_ih1 = (const float*)d_in[7];
    const float* b_hh1 = (const float*)d_in[8];
    const float* fc_w  = (const float*)d_in[9];
    const float* fc_b  = (const float*)d_in[10];
    float* out = (float*)d_out;

    dim3 grid(BATCH / BC);
    lstm_layer_kernel<0><<<grid, NT>>>(x, w_ih0, w_hh0, b_ih0, b_hh0,
                                       nullptr, nullptr, nullptr);
    lstm_layer_kernel<1><<<grid, NT>>>(nullptr, w_ih1, w_hh1, b_ih1, b_hh1,
                                       fc_w, fc_b, out);
}

// round 4
// speedup vs baseline: 1.4209x; 1.2030x over previous
#include <cuda_runtime.h>
#include <cuda_bf16.h>
#include <math.h>

#define BATCH 1024
#define SEQ   512
#define HID   64
#define GATES 256   // 4*HID
#define BC    8     // batch rows per CTA
#define NT    512   // threads per CTA

// Scratch: layer-0 hidden sequence (input to layer 1).
__device__ float g_h1[(size_t)BATCH * SEQ * HID];

typedef unsigned long long u64;

// Packed fp32x2 FMA: d = a*b + d  (Blackwell FFMA2, only reachable via PTX).
__device__ __forceinline__ void ffma2(u64& d, u64 a, u64 b) {
    asm("fma.rn.f32x2 %0, %1, %2, %0;" : "+l"(d) : "l"(a), "l"(b));
}
__device__ __forceinline__ u64 pack2(float lo, float hi) {
    u64 r; asm("mov.b64 %0, {%1, %2};" : "=l"(r) : "f"(lo), "f"(hi)); return r;
}
__device__ __forceinline__ float2 unpack2(u64 v) {
    float lo, hi; asm("mov.b64 {%0, %1}, %2;" : "=f"(lo), "=f"(hi) : "l"(v));
    return make_float2(lo, hi);
}

// Fast activations (MUFU based, err ~1e-6; budget is 1e-3).
__device__ __forceinline__ float sig_fast(float x) {
    return __fdividef(1.0f, 1.0f + __expf(-x));
}
__device__ __forceinline__ float tanh_fast(float x) {
    float e = __expf(-2.0f * fabsf(x));
    float t = __fdividef(1.0f - e, 1.0f + e);
    return copysignf(t, x);
}

// One LSTM layer, fused over all SEQ steps. Each CTA owns BC batch rows.
// Thread decomposition: gp = tid&127 -> gate rows {2gp, 2gp+1};
// q = tid>>7 -> k-range [16q, 16q+16). Each thread covers all 8 batches.
// Each 16B x/h load feeds 4 FFMA2 (2 gates x packed pair) -> 4:1 FMA:LDS.
template<int LAYER>
__global__ void __launch_bounds__(NT, 1) lstm_layer_kernel(
    const float* __restrict__ xin,
    const float* __restrict__ w_ih,   // [256][64]
    const float* __restrict__ w_hh,   // [256][64]
    const float* __restrict__ b_ih,   // [256]
    const float* __restrict__ b_hh,   // [256]
    const float* __restrict__ fc_w,   // [64]  (LAYER==1 only)
    const float* __restrict__ fc_b,   // [1]   (LAYER==1 only)
    float* __restrict__ out)          // [BATCH] (LAYER==1 only)
{
    __shared__ __align__(16) float sx[2][BC][HID];       // double-buffered x_t
    __shared__ __align__(16) float sh[BC][HID];          // h_{t-1}
    __shared__ __align__(16) float spre[4][BC][GATES];   // split-K(4) partials

    const int tid = threadIdx.x;
    const int gp  = tid & 127;         // gate pair -> rows 2gp, 2gp+1
    const int q   = tid >> 7;          // k quarter
    const int kb  = q * 16;
    const int b0  = blockIdx.x * BC;
    const int bb  = tid >> 6;          // cell batch index (phase 2 / loads)
    const int jj  = tid & 63;          // cell hidden index

    const float* in = (LAYER == 0) ? xin : g_h1;
    const int g0 = 2 * gp, g1 = 2 * gp + 1;

    // Weights in registers: 2 gates x 8 u64 pairs x 2 matrices = 32 u64.
    u64 wih2[2][8], whh2[2][8];
#pragma unroll
    for (int k = 0; k < 8; k++) {
        float2 a0 = *(const float2*)&w_ih[g0 * HID + kb + 2 * k];
        float2 a1 = *(const float2*)&w_ih[g1 * HID + kb + 2 * k];
        float2 h0 = *(const float2*)&w_hh[g0 * HID + kb + 2 * k];
        float2 h1 = *(const float2*)&w_hh[g1 * HID + kb + 2 * k];
        wih2[0][k] = pack2(a0.x, a0.y);
        wih2[1][k] = pack2(a1.x, a1.y);
        whh2[0][k] = pack2(h0.x, h0.y);
        whh2[1][k] = pack2(h1.x, h1.y);
    }
    const float bias0 = (q == 0) ? (b_ih[g0] + b_hh[g0]) : 0.0f;
    const float bias1 = (q == 0) ? (b_ih[g1] + b_hh[g1]) : 0.0f;

    // h0 = c0 = 0.  Each thread owns cell (bb, jj) in phase 2.
    if (tid < BC * HID) ((float*)sh)[tid] = 0.0f;
    float c = 0.0f;

    // Preload x_0: one float per thread, coalesced.
    sx[0][bb][jj] = in[((size_t)(b0 + bb) * SEQ) * HID + jj];
    __syncthreads();

    for (int t = 0; t < SEQ; t++) {
        const int cur = t & 1;

        // Prefetch x_{t+1}; ~600cyc LDG latency hidden under the FMA phase.
        if (t + 1 < SEQ)
            sx[cur ^ 1][bb][jj] = in[((size_t)(b0 + bb) * SEQ + (t + 1)) * HID + jj];

        // Phase 1: partial pre-activations for 2 gate rows over k quarter.
        u64 acc0[BC], acc1[BC];
#pragma unroll
        for (int b = 0; b < BC; b++) { acc0[b] = 0ull; acc1[b] = 0ull; }

#pragma unroll
        for (int k = 0; k < 16; k += 4) {
            const int p = k >> 1;
#pragma unroll
            for (int b = 0; b < BC; b++) {
                const ulonglong2 xv = *(const ulonglong2*)&sx[cur][b][kb + k];
                const ulonglong2 hv = *(const ulonglong2*)&sh[b][kb + k];
                ffma2(acc0[b], xv.x, wih2[0][p]);
                ffma2(acc0[b], xv.y, wih2[0][p + 1]);
                ffma2(acc0[b], hv.x, whh2[0][p]);
                ffma2(acc0[b], hv.y, whh2[0][p + 1]);
                ffma2(acc1[b], xv.x, wih2[1][p]);
                ffma2(acc1[b], xv.y, wih2[1][p + 1]);
                ffma2(acc1[b], hv.x, whh2[1][p]);
                ffma2(acc1[b], hv.y, whh2[1][p + 1]);
            }
        }
#pragma unroll
        for (int b = 0; b < BC; b++) {
            const float2 s0 = unpack2(acc0[b]);
            const float2 s1 = unpack2(acc1[b]);
            *(float2*)&spre[q][b][g0] =
                make_float2(s0.x + s0.y + bias0, s1.x + s1.y + bias1);
        }
        __syncthreads();

        // Phase 2: one cell per thread; sum the 4 split-K planes.
        {
            float pi = 0.f, pf = 0.f, pg = 0.f, po = 0.f;
#pragma unroll
            for (int s = 0; s < 4; s++) {
                pi += spre[s][bb][jj];
                pf += spre[s][bb][64 + jj];
                pg += spre[s][bb][128 + jj];
                po += spre[s][bb][192 + jj];
            }
            const float iv = sig_fast(pi);
            const float fv = sig_fast(pf);
            const float gv = tanh_fast(pg);
            const float ov = sig_fast(po);
            c = fv * c + iv * gv;
            const float h = ov * tanh_fast(c);
            sh[bb][jj] = h;
            if (LAYER == 0)
                g_h1[((size_t)(b0 + bb) * SEQ + t) * HID + jj] = h;
        }
        __syncthreads();
    }

    // Fused FC head on the final hidden state (layer 1 only).
    if (LAYER == 1 && tid < 256) {
        const int wrp  = tid >> 5;
        const int lane = tid & 31;
        float v = fc_w[lane] * sh[wrp][lane] + fc_w[lane + 32] * sh[wrp][lane + 32];
#pragma unroll
        for (int off = 16; off; off >>= 1)
            v += __shfl_down_sync(0xffffffffu, v, off);
        if (lane == 0) out[b0 + wrp] = v + fc_b[0];
    }
}

extern "C" void kernel_launch(void* const* d_in, const int* in_sizes, int n_in,
                              void* d_out, int out_size)
{
    const float* x     = (const float*)d_in[0];
    const float* w_ih0 = (const float*)d_in[1];
    const float* w_hh0 = (const float*)d_in[2];
    const float* b_ih0 = (const float*)d_in[3];
    const float* b_hh0 = (const float*)d_in[4];
    const float* w_ih1 = (const float*)d_in[5];
    const float* w_hh1 = (const float*)d_in[6];
    const float* b_ih1 = (const float*)d_in[7];
    const float* b_hh1 = (const float*)d_in[8];
    const float* fc_w  = (const float*)d_in[9];
    const float* fc_b  = (const float*)d_in[10];
    float* out = (float*)d_out;

    dim3 grid(BATCH / BC);
    lstm_layer_kernel<0><<<grid, NT>>>(x, w_ih0, w_hh0, b_ih0, b_hh0,
                                       nullptr, nullptr, nullptr);
    lstm_layer_kernel<1><<<grid, NT>>>(nullptr, w_ih1, w_hh1, b_ih1, b_hh1,
                                       fc_w, fc_b, out);
}

// round 5
// speedup vs baseline: 1.5692x; 1.1044x over previous
#include <cuda_runtime.h>
#include <cuda_bf16.h>
#include <math.h>

#define BATCH 1024
#define SEQ   512
#define HID   64
#define GATES 256   // 4*HID
#define BC    8     // batch rows per CTA (2 groups of 4)
#define NT    512   // threads per CTA

// Scratch: layer-0 hidden sequence (input to layer 1).
__device__ float g_h1[(size_t)BATCH * SEQ * HID];

typedef unsigned long long u64;

// Packed fp32x2 FMA (Blackwell FFMA2, only reachable via PTX).
__device__ __forceinline__ void ffma2(u64& d, u64 a, u64 b) {
    asm("fma.rn.f32x2 %0, %1, %2, %0;" : "+l"(d) : "l"(a), "l"(b));
}
__device__ __forceinline__ u64 pack2(float lo, float hi) {
    u64 r; asm("mov.b64 %0, {%1, %2};" : "=l"(r) : "f"(lo), "f"(hi)); return r;
}
__device__ __forceinline__ float2 unpack2(u64 v) {
    float lo, hi; asm("mov.b64 {%0, %1}, %2;" : "=f"(lo), "=f"(hi) : "l"(v));
    return make_float2(lo, hi);
}

// Fast activations (MUFU based, err ~1e-6; budget is 1e-3).
__device__ __forceinline__ float sig_fast(float x) {
    return __fdividef(1.0f, 1.0f + __expf(-x));
}
__device__ __forceinline__ float tanh_fast(float x) {
    float e = __expf(-2.0f * fabsf(x));
    float t = __fdividef(1.0f - e, 1.0f + e);
    return copysignf(t, x);
}

// Two-group software-pipelined LSTM layer. Each CTA owns 8 batch rows,
// split into group A (0-3) and group B (4-7). Each barrier interval runs
// phase1 (gate GEMV, FFMA2) of one group overlapped with phase2 (cell
// update, MUFU) of the other, so the FMA pipe never drains.
// Thread decomposition for phase1: gp=tid&127 -> gate rows {2gp,2gp+1},
// q=tid>>7 -> k-range [16q,16q+16). Phase2: tid<256 -> group A cell,
// tid>=256 -> group B cell.
template<int LAYER>
__global__ void __launch_bounds__(NT, 1) lstm_layer_kernel(
    const float* __restrict__ xin,
    const float* __restrict__ w_ih,   // [256][64]
    const float* __restrict__ w_hh,   // [256][64]
    const float* __restrict__ b_ih,   // [256]
    const float* __restrict__ b_hh,   // [256]
    const float* __restrict__ fc_w,   // [64]  (LAYER==1 only)
    const float* __restrict__ fc_b,   // [1]   (LAYER==1 only)
    float* __restrict__ out)          // [BATCH] (LAYER==1 only)
{
    __shared__ __align__(16) float sx[2][2][4][HID];     // [group][buf][b][j]
    __shared__ __align__(16) float sh[BC][HID];          // h_{t-1} (A: 0-3, B: 4-7)
    __shared__ __align__(16) float spr[2][4][4][GATES];  // [group][kq][b][gate]

    const int tid = threadIdx.x;
    const int gp  = tid & 127;         // gate pair -> rows 2gp, 2gp+1
    const int q   = tid >> 7;          // k quarter
    const int kb  = q * 16;
    const int b0  = blockIdx.x * BC;
    const int g0  = 2 * gp, g1 = 2 * gp + 1;

    // Phase-2 role: group this thread serves, and its cell.
    const int pg = tid >> 8;           // 0 = A, 1 = B
    const int ci = tid & 255;
    const int cb = ci >> 6;            // local batch 0..3
    const int cj = ci & 63;            // hidden index

    const float* in = (LAYER == 0) ? xin : g_h1;

    // Weights in registers: 2 gates x 8 f32x2 pairs x 2 matrices.
    u64 wih2[2][8], whh2[2][8];
#pragma unroll
    for (int k = 0; k < 8; k++) {
        float2 a0 = *(const float2*)&w_ih[g0 * HID + kb + 2 * k];
        float2 a1 = *(const float2*)&w_ih[g1 * HID + kb + 2 * k];
        float2 h0 = *(const float2*)&w_hh[g0 * HID + kb + 2 * k];
        float2 h1 = *(const float2*)&w_hh[g1 * HID + kb + 2 * k];
        wih2[0][k] = pack2(a0.x, a0.y);
        wih2[1][k] = pack2(a1.x, a1.y);
        whh2[0][k] = pack2(h0.x, h0.y);
        whh2[1][k] = pack2(h1.x, h1.y);
    }
    // Phase-2 biases (per owned cell).
    const float bi = b_ih[cj]       + b_hh[cj];
    const float bf = b_ih[64 + cj]  + b_hh[64 + cj];
    const float bg = b_ih[128 + cj] + b_hh[128 + cj];
    const float bo = b_ih[192 + cj] + b_hh[192 + cj];
    float c = 0.0f;

    // Init h=0 and load x(A,0), x(B,0).
    ((float*)sh)[tid] = 0.0f;
    sx[pg][0][cb][cj] = in[((size_t)(b0 + pg * 4 + cb) * SEQ) * HID + cj];
    __syncthreads();

    // Phase1 macro: gate pre-activations for one group (4 batches).
#define P1(grp, buf)                                                          \
    {                                                                         \
        u64 a0[4], a1[4];                                                     \
        _Pragma("unroll")                                                     \
        for (int b = 0; b < 4; b++) { a0[b] = 0ull; a1[b] = 0ull; }           \
        _Pragma("unroll")                                                     \
        for (int k = 0; k < 16; k += 4) {                                     \
            const int p = k >> 1;                                             \
            _Pragma("unroll")                                                 \
            for (int b = 0; b < 4; b++) {                                     \
                const ulonglong2 xv = *(const ulonglong2*)&sx[grp][buf][b][kb + k]; \
                const ulonglong2 hv = *(const ulonglong2*)&sh[(grp) * 4 + b][kb + k]; \
                ffma2(a0[b], xv.x, wih2[0][p]);                               \
                ffma2(a0[b], xv.y, wih2[0][p + 1]);                           \
                ffma2(a0[b], hv.x, whh2[0][p]);                               \
                ffma2(a0[b], hv.y, whh2[0][p + 1]);                           \
                ffma2(a1[b], xv.x, wih2[1][p]);                               \
                ffma2(a1[b], xv.y, wih2[1][p + 1]);                           \
                ffma2(a1[b], hv.x, whh2[1][p]);                               \
                ffma2(a1[b], hv.y, whh2[1][p + 1]);                           \
            }                                                                 \
        }                                                                     \
        _Pragma("unroll")                                                     \
        for (int b = 0; b < 4; b++) {                                         \
            const float2 s0 = unpack2(a0[b]);                                 \
            const float2 s1 = unpack2(a1[b]);                                 \
            *(float2*)&spr[grp][q][b][g0] =                                   \
                make_float2(s0.x + s0.y, s1.x + s1.y);                        \
        }                                                                     \
    }

    // Phase2 macro: cell update for this thread's owned cell in group `grp`.
#define P2(grp, t)                                                            \
    {                                                                         \
        float pi = bi, pf = bf, pgx = bg, po = bo;                            \
        _Pragma("unroll")                                                     \
        for (int s = 0; s < 4; s++) {                                         \
            pi  += spr[grp][s][cb][cj];                                       \
            pf  += spr[grp][s][cb][64 + cj];                                  \
            pgx += spr[grp][s][cb][128 + cj];                                 \
            po  += spr[grp][s][cb][192 + cj];                                 \
        }                                                                     \
        const float iv = sig_fast(pi);                                        \
        const float fv = sig_fast(pf);                                        \
        const float gv = tanh_fast(pgx);                                      \
        const float ov = sig_fast(po);                                        \
        c = fv * c + iv * gv;                                                 \
        const float h = ov * tanh_fast(c);                                    \
        sh[(grp) * 4 + cb][cj] = h;                                           \
        if (LAYER == 0)                                                       \
            g_h1[((size_t)(b0 + (grp) * 4 + cb) * SEQ + (t)) * HID + cj] = h; \
    }

    // Prologue: P1(A, t=0).
    P1(0, 0);
    __syncthreads();

    for (int t = 0; t < SEQ; t++) {
        const int nb = (t + 1) & 1;

        // ── Interval 1: P1(B,t) + P2(A,t) + prefetch x(A,t+1) ──
        float xp;
        if (t + 1 < SEQ && tid >= 256)
            xp = in[((size_t)(b0 + cb) * SEQ + (t + 1)) * HID + cj];
        P1(1, t & 1);
        if (tid < 256) P2(0, t);
        if (t + 1 < SEQ && tid >= 256) sx[0][nb][cb][cj] = xp;
        __syncthreads();

        // ── Interval 2: P1(A,t+1) + P2(B,t) + prefetch x(B,t+1) ──
        if (t + 1 < SEQ && tid < 256)
            xp = in[((size_t)(b0 + 4 + cb) * SEQ + (t + 1)) * HID + cj];
        if (t + 1 < SEQ) P1(0, nb);
        if (tid >= 256) P2(1, t);
        if (t + 1 < SEQ && tid < 256) sx[1][nb][cb][cj] = xp;
        __syncthreads();
    }

    // Fused FC head on the final hidden state (layer 1 only).
    if (LAYER == 1 && tid < 256) {
        const int wrp  = tid >> 5;
        const int lane = tid & 31;
        float v = fc_w[lane] * sh[wrp][lane] + fc_w[lane + 32] * sh[wrp][lane + 32];
#pragma unroll
        for (int off = 16; off; off >>= 1)
            v += __shfl_down_sync(0xffffffffu, v, off);
        if (lane == 0) out[b0 + wrp] = v + fc_b[0];
    }
#undef P1
#undef P2
}

extern "C" void kernel_launch(void* const* d_in, const int* in_sizes, int n_in,
                              void* d_out, int out_size)
{
    const float* x     = (const float*)d_in[0];
    const float* w_ih0 = (const float*)d_in[1];
    const float* w_hh0 = (const float*)d_in[2];
    const float* b_ih0 = (const float*)d_in[3];
    const float* b_hh0 = (const float*)d_in[4];
    const float* w_ih1 = (const float*)d_in[5];
    const float* w_hh1 = (const float*)d_in[6];
    const float* b_ih1 = (const float*)d_in[7];
    const float* b_hh1 = (const float*)d_in[8];
    const float* fc_w  = (const float*)d_in[9];
    const float* fc_b  = (const float*)d_in[10];
    float* out = (float*)d_out;

    dim3 grid(BATCH / BC);
    lstm_layer_kernel<0><<<grid, NT>>>(x, w_ih0, w_hh0, b_ih0, b_hh0,
                                       nullptr, nullptr, nullptr);
    lstm_layer_kernel<1><<<grid, NT>>>(nullptr, w_ih1, w_hh1, b_ih1, b_hh1,
                                       fc_w, fc_b, out);
}

// round 6
// speedup vs baseline: 3.1209x; 1.9888x over previous
#include <cuda_runtime.h>
#include <cuda_bf16.h>
#include <math.h>

#define BATCH 1024
#define SEQ   512
#define HID   64
#define GATES 256
#define BC    8
#define NT    512
// padded strides (floats): stride%32==4 -> bank(4b + col) all-distinct for
// the mma A-fragment access pattern (b=lane>>2, col=lane&3 .. +4)
#define HS    68
#define PS    264

// Scratch: layer-0 hidden sequence (input to layer 1).
__device__ float g_h1[(size_t)BATCH * SEQ * HID];

// RNA round fp32 -> tf32 bit pattern (kept in a 32-bit reg).
__device__ __forceinline__ unsigned tf32r(float f) {
    unsigned u; asm("cvt.rna.tf32.f32 %0, %1;" : "=r"(u) : "f"(f)); return u;
}

// m16n8k8 tf32 mma, rows 8-15 of A are zero (a1 = a3 = 0).
__device__ __forceinline__ void mma_tf32(float& d0, float& d1, float& d2, float& d3,
                                         unsigned a0, unsigned a2,
                                         unsigned b0, unsigned b1) {
    const unsigned z = 0u;
    asm volatile(
        "mma.sync.aligned.m16n8k8.row.col.f32.tf32.tf32.f32 "
        "{%0,%1,%2,%3}, {%4,%5,%6,%7}, {%8,%9}, {%0,%1,%2,%3};"
        : "+f"(d0), "+f"(d1), "+f"(d2), "+f"(d3)
        : "r"(a0), "r"(z), "r"(a2), "r"(z), "r"(b0), "r"(b1));
}

// Fast activations (MUFU based, err ~1e-6).
__device__ __forceinline__ float sig_fast(float x) {
    return __fdividef(1.0f, 1.0f + __expf(-x));
}
__device__ __forceinline__ float tanh_fast(float x) {
    float e = __expf(-2.0f * fabsf(x));
    float t = __fdividef(1.0f - e, 1.0f + e);
    return copysignf(t, x);
}

// Tensor-core LSTM layer. Each CTA: 8 batch rows, 512 threads (16 warps).
// Per step: G[8][256] = [h | x_t](8x128) @ B(128x256) via m16n8k8 tf32 mma
// (K-concat: B rows 0-63 = w_hh^T, rows 64-127 = w_ih^T). B-fragments are
// register-resident per warp (warp w owns gate columns [16w,16w+16)).
// Then P2: one cell per thread (MUFU activations), h written tf32-rounded.
template<int LAYER>
__global__ void __launch_bounds__(NT, 1) lstm_layer_kernel(
    const float* __restrict__ xin,
    const float* __restrict__ w_ih,   // [256][64]
    const float* __restrict__ w_hh,   // [256][64]
    const float* __restrict__ b_ih,
    const float* __restrict__ b_hh,
    const float* __restrict__ fc_w,
    const float* __restrict__ fc_b,
    float* __restrict__ out)
{
    __shared__ __align__(16) float sh[BC * HS];        // h_{t-1} (tf32 bits)
    __shared__ __align__(16) float sx[2][BC * HS];     // x_t (tf32 bits), dbuf
    __shared__ __align__(16) float spre[BC * PS];      // gate pre-acts

    const int tid  = threadIdx.x;
    const int w    = tid >> 5;
    const int lane = tid & 31;
    const int grp  = lane >> 2;      // mma group id = batch row (0..7)
    const int tg   = lane & 3;       // thread-in-group
    const int b0   = blockIdx.x * BC;

    // P2 cell: (b, j)
    const int b = tid >> 6;
    const int j = tid & 63;

    const float* in = (LAYER == 0) ? xin : g_h1;

    // ── B-fragments (weights), loaded once, RNA-rounded to tf32.
    // warp w covers n in [16w, 16w+16): nn selects 8-col tile.
    // b0reg: k = 8kk+tg, b1reg: k = 8kk+tg+4;  n = 16w + 8nn + grp.
    unsigned bfr[16][2][2];
#pragma unroll
    for (int kk = 0; kk < 16; kk++) {
#pragma unroll
        for (int nn = 0; nn < 2; nn++) {
            const int n = 16 * w + 8 * nn + grp;
#pragma unroll
            for (int hB = 0; hB < 2; hB++) {
                const int k = 8 * kk + tg + 4 * hB;
                const float v = (k < HID) ? w_hh[n * HID + k]
                                          : w_ih[n * HID + (k - HID)];
                bfr[kk][nn][hB] = tf32r(v);
            }
        }
    }

    // P2 biases and state.
    const float bi = b_ih[j]           + b_hh[j];
    const float bf = b_ih[HID + j]     + b_hh[HID + j];
    const float bg = b_ih[2 * HID + j] + b_hh[2 * HID + j];
    const float bo = b_ih[3 * HID + j] + b_hh[3 * HID + j];
    float c = 0.0f;

    // Init h = 0; load + convert x_0.
    for (int i = tid; i < BC * HS; i += NT) sh[i] = 0.0f;
    sx[0][b * HS + j] = __uint_as_float(
        tf32r(in[((size_t)(b0 + b) * SEQ) * HID + j]));
    __syncthreads();

    for (int t = 0; t < SEQ; t++) {
        const int cur = t & 1, nb = cur ^ 1;

        // Prefetch x_{t+1} (LDG latency hidden under mma phase).
        float xp = 0.0f;
        if (t + 1 < SEQ)
            xp = in[((size_t)(b0 + b) * SEQ + (t + 1)) * HID + j];

        // ── mma phase: acc[nn] = [h|x] @ B  (k 0-63 from sh, 64-127 from sx)
        float d[2][4];
#pragma unroll
        for (int nn = 0; nn < 2; nn++)
#pragma unroll
            for (int i = 0; i < 4; i++) d[nn][i] = 0.0f;

#pragma unroll
        for (int kk = 0; kk < 8; kk++) {
            const unsigned a0 = __float_as_uint(sh[grp * HS + 8 * kk + tg]);
            const unsigned a2 = __float_as_uint(sh[grp * HS + 8 * kk + tg + 4]);
            mma_tf32(d[0][0], d[0][1], d[0][2], d[0][3], a0, a2,
                     bfr[kk][0][0], bfr[kk][0][1]);
            mma_tf32(d[1][0], d[1][1], d[1][2], d[1][3], a0, a2,
                     bfr[kk][1][0], bfr[kk][1][1]);
        }
#pragma unroll
        for (int kk = 0; kk < 8; kk++) {
            const unsigned a0 = __float_as_uint(sx[cur][grp * HS + 8 * kk + tg]);
            const unsigned a2 = __float_as_uint(sx[cur][grp * HS + 8 * kk + tg + 4]);
            mma_tf32(d[0][0], d[0][1], d[0][2], d[0][3], a0, a2,
                     bfr[kk + 8][0][0], bfr[kk + 8][0][1]);
            mma_tf32(d[1][0], d[1][1], d[1][2], d[1][3], a0, a2,
                     bfr[kk + 8][1][0], bfr[kk + 8][1][1]);
        }

        // Store D rows 0-7: thread holds G[grp][n0], G[grp][n0+1].
#pragma unroll
        for (int nn = 0; nn < 2; nn++) {
            const int n0 = 16 * w + 8 * nn + 2 * tg;
            *(float2*)&spre[grp * PS + n0] = make_float2(d[nn][0], d[nn][1]);
        }
        __syncthreads();

        // ── P2: one cell per thread.
        {
            const float pi  = bi + spre[b * PS + j];
            const float pf  = bf + spre[b * PS + HID + j];
            const float pg  = bg + spre[b * PS + 2 * HID + j];
            const float po  = bo + spre[b * PS + 3 * HID + j];
            const float iv = sig_fast(pi);
            const float fv = sig_fast(pf);
            const float gv = tanh_fast(pg);
            const float ov = sig_fast(po);
            c = fv * c + iv * gv;
            const float h = ov * tanh_fast(c);
            sh[b * HS + j] = __uint_as_float(tf32r(h));
            if (LAYER == 0)
                g_h1[((size_t)(b0 + b) * SEQ + t) * HID + j] = h;
            if (t + 1 < SEQ)
                sx[nb][b * HS + j] = __uint_as_float(tf32r(xp));
        }
        __syncthreads();
    }

    // Fused FC head (layer 1 only).
    if (LAYER == 1 && tid < 256) {
        const int wrp = tid >> 5, ln = tid & 31;
        float v = fc_w[ln] * sh[wrp * HS + ln]
                + fc_w[ln + 32] * sh[wrp * HS + ln + 32];
#pragma unroll
        for (int off = 16; off; off >>= 1)
            v += __shfl_down_sync(0xffffffffu, v, off);
        if (ln == 0) out[b0 + wrp] = v + fc_b[0];
    }
}

extern "C" void kernel_launch(void* const* d_in, const int* in_sizes, int n_in,
                              void* d_out, int out_size)
{
    const float* x     = (const float*)d_in[0];
    const float* w_ih0 = (const float*)d_in[1];
    const float* w_hh0 = (const float*)d_in[2];
    const float* b_ih0 = (const float*)d_in[3];
    const float* b_hh0 = (const float*)d_in[4];
    const float* w_ih1 = (const float*)d_in[5];
    const float* w_hh1 = (const float*)d_in[6];
    const float* b_ih1 = (const float*)d_in[7];
    const float* b_hh1 = (const float*)d_in[8];
    const float* fc_w  = (const float*)d_in[9];
    const float* fc_b  = (const float*)d_in[10];
    float* out = (float*)d_out;

    dim3 grid(BATCH / BC);
    lstm_layer_kernel<0><<<grid, NT>>>(x, w_ih0, w_hh0, b_ih0, b_hh0,
                                       nullptr, nullptr, nullptr);
    lstm_layer_kernel<1><<<grid, NT>>>(nullptr, w_ih1, w_hh1, b_ih1, b_hh1,
                                       fc_w, fc_b, out);
}